// round 4
// baseline (speedup 1.0000x reference)
#include <cuda_runtime.h>
#include <cstdint>
#include <math.h>

#define SQ   400
#define BB   128
#define HH   512
#define EE   300
#define G3   1536
#define NCOL 3072

typedef unsigned long long u64;
typedef unsigned int       u32;

__device__ float g_gi[(size_t)SQ * NCOL * BB];      // [t][col(3072)][b(128)]
__device__ float g_y0[(size_t)SQ * 1024 * BB];      // [t][k(1024)][b(128)]
__device__ float g_h[2][2][HH][BB];                 // [buf][dir][k][b]  (non-duplicated)
__device__ unsigned g_bar;

__device__ __forceinline__ void fma2(u64 &d, u64 a, u64 b) {
    asm("fma.rn.f32x2 %0, %1, %2, %0;" : "+l"(d) : "l"(a), "l"(b));
}
__device__ __forceinline__ u64 pack2(float x, float y) {
    u64 r; asm("mov.b64 %0, {%1, %2};" : "=l"(r) : "f"(x), "f"(y)); return r;
}
__device__ __forceinline__ float2 unpack2(u64 v) {
    float2 f;
    f.x = __uint_as_float((unsigned)(v & 0xffffffffull));
    f.y = __uint_as_float((unsigned)(v >> 32));
    return f;
}

__global__ void init_kernel() {
    float* p = &g_h[0][0][0][0];
    size_t n = 2ull * 2 * HH * BB;
    for (size_t i = blockIdx.x * blockDim.x + threadIdx.x; i < n; i += (size_t)gridDim.x * blockDim.x)
        p[i] = 0.0f;
    if (blockIdx.x == 0 && threadIdx.x == 0) g_bar = 0u;
}

// ---------------- big input GEMM (unchanged from passing round) ----------------
template <bool GATHER>
__global__ __launch_bounds__(256, 2) void gemm_kernel(
    const float* __restrict__ Aemb, const int* __restrict__ X,
    const float* __restrict__ W, const float* __restrict__ bias, int K)
{
    __shared__ __align__(16) float As[2][8][256];
    __shared__ __align__(16) float Bs[2][8][128];

    const int t     = blockIdx.y;
    const int nbase = blockIdx.x * 128;
    const int tid   = threadIdx.x;
    const int tx    = tid & 15;
    const int ty    = tid >> 4;
    const int lm    = tid >> 1;
    const int lk    = (tid & 1) * 4;
    const int kk8   = tid >> 5;
    const int b0    = (tid & 31) * 4;

    const float* arow;
    if (GATHER) arow = Aemb + (size_t)X[t * 128 + lm] * K;
    else        arow = g_y0 + (size_t)t * 1024 * 128;
    const float* brow = W + (size_t)(nbase + lm) * K;

    u64 acc[8][4];
#pragma unroll
    for (int r = 0; r < 8; r++)
#pragma unroll
        for (int c = 0; c < 4; c++) acc[r][c] = 0ull;

    const int nk = (K + 7) >> 3;

    float4 a4, b4;
    if (GATHER) a4 = (lk < K) ? *(const float4*)(arow + lk) : make_float4(0,0,0,0);
    else        a4 = *(const float4*)(arow + (size_t)kk8 * 128 + b0);
    b4 = (lk < K) ? *(const float4*)(brow + lk) : make_float4(0,0,0,0);

    for (int it = 0; it < nk; it++) {
        const int buf = it & 1;
#pragma unroll
        for (int i = 0; i < 4; i++) {
            float va = (&a4.x)[i];
            if (GATHER) *(u64*)&As[buf][lk + i][2 * lm] = pack2(va, va);
            else        *(u64*)&As[buf][kk8][2 * (b0 + i)] = pack2(va, va);
            Bs[buf][lk + i][lm] = (&b4.x)[i];
        }
        __syncthreads();
        if (it + 1 < nk) {
            int kn = (it + 1) * 8 + lk;
            if (GATHER) a4 = (kn < K) ? *(const float4*)(arow + kn) : make_float4(0,0,0,0);
            else        a4 = *(const float4*)(arow + ((size_t)(it + 1) * 8 + kk8) * 128 + b0);
            b4 = (kn < K) ? *(const float4*)(brow + kn) : make_float4(0,0,0,0);
        }
#pragma unroll
        for (int kk = 0; kk < 8; kk++) {
            u64 ad[8];
#pragma unroll
            for (int r2 = 0; r2 < 4; r2++) {
                ulonglong2 aa = *(const ulonglong2*)&As[buf][kk][ty * 16 + r2 * 4];
                ad[2 * r2] = aa.x; ad[2 * r2 + 1] = aa.y;
            }
            u64 bp[4];
#pragma unroll
            for (int c2 = 0; c2 < 2; c2++) {
                ulonglong2 bv = *(const ulonglong2*)&Bs[buf][kk][tx * 8 + c2 * 4];
                bp[2 * c2] = bv.x; bp[2 * c2 + 1] = bv.y;
            }
#pragma unroll
            for (int r = 0; r < 8; r++)
#pragma unroll
                for (int c = 0; c < 4; c++) fma2(acc[r][c], ad[r], bp[c]);
        }
        __syncthreads();
    }

    float* cbase = g_gi + ((size_t)t * NCOL + nbase + tx * 8) * 128 + ty * 8;
#pragma unroll
    for (int c = 0; c < 8; c++) {
        float bv = bias[nbase + tx * 8 + c];
        float v[8];
#pragma unroll
        for (int r = 0; r < 8; r++) {
            float2 f = unpack2(acc[r][c >> 1]);
            v[r] = ((c & 1) ? f.y : f.x) + bv;
        }
        float4* dst = (float4*)(cbase + (size_t)c * 128);
        dst[0] = make_float4(v[0], v[1], v[2], v[3]);
        dst[1] = make_float4(v[4], v[5], v[6], v[7]);
    }
}

// ---------------- persistent recurrence, smem-staged h ----------------
// 128 CTAs: dir = cta>>6, jbase = (cta&63)*8.  128 threads: j = tid>>4 (0..7),
// q = tid&15 -> b quads {4q..4q+3, 4q+64..4q+67}.  accs: 3 gates x 4 b-pairs.
// smem: w_s = dup weight pairs u64[512][24] (96KB); h_s = 2 x 32KB chunk buffers.
#define CHUNK_K 64
#define W_S_BYTES (512 * 24 * 8)
#define H_S_BYTES (CHUNK_K * 128 * 4)
#define RECUR_SMEM (W_S_BYTES + 2 * H_S_BYTES)

__device__ __forceinline__ void stage_chunk(u32 sdst, const float* src, int tid) {
#pragma unroll
    for (int i = 0; i < 16; i++) {
        asm volatile("cp.async.cg.shared.global [%0], [%1], 16;"
                     :: "r"(sdst + (u32)(tid * 16 + i * 2048)),
                        "l"(src + tid * 4 + i * 512) : "memory");
    }
    asm volatile("cp.async.commit_group;" ::: "memory");
}
__device__ __forceinline__ void wait_stage() {
    asm volatile("cp.async.wait_group 0;" ::: "memory");
}

template <bool WRITE_Y>
__global__ __launch_bounds__(128, 1) void recur_kernel(
    const float* __restrict__ Whh, const float* __restrict__ bhh)
{
    extern __shared__ __align__(16) char smem_raw[];
    u64*   w_s = (u64*)smem_raw;                       // [k][24 rows] dup pairs
    char*  h_s = smem_raw + W_S_BYTES;                 // 2 x [64][128] floats
    u32 h_s_u32 = (u32)__cvta_generic_to_shared(h_s);

    const int cta   = blockIdx.x;
    const int d     = cta >> 6;
    const int jbase = (cta & 63) * 8;
    const int tid   = threadIdx.x;
    const int j     = tid >> 4;
    const int q     = tid & 15;
    const int jg    = jbase + j;
    const int b0    = 4 * q;
    const int b1    = 4 * q + 64;

    // fill duplicated weight pairs: w_s[k*24 + g*8 + jj] = (w,w)
    for (int idx = tid; idx < 512 * 24; idx += 128) {
        int r = idx >> 9, k = idx & 511;         // r = g*8+jj
        int g = r >> 3, jj = r & 7;
        float v = Whh[((size_t)d * G3 + g * HH + jbase + jj) * HH + k];
        w_s[(size_t)k * 24 + r] = pack2(v, v);
    }
    float bh[3];
#pragma unroll
    for (int g = 0; g < 3; g++) bh[g] = bhh[(size_t)d * G3 + g * HH + jg];
    __syncthreads();

    float hold[8];
#pragma unroll
    for (int e = 0; e < 8; e++) hold[e] = 0.0f;

    for (int t = 0; t < SQ; t++) {
        const int pr = t & 1, pw = pr ^ 1;
        const float* hsrc = &g_h[pr][d][0][0];

        stage_chunk(h_s_u32, hsrc, tid);

        // hoist gi gate loads (independent of h)
        const float* gbase = g_gi + (size_t)t * NCOL * 128 + (size_t)(d * G3 + jg) * 128;
        float4 gr0 = __ldg((const float4*)(gbase + b0));
        float4 gr1 = __ldg((const float4*)(gbase + b1));
        float4 gz0 = __ldg((const float4*)(gbase + (size_t)HH * 128 + b0));
        float4 gz1 = __ldg((const float4*)(gbase + (size_t)HH * 128 + b1));
        float4 gn0 = __ldg((const float4*)(gbase + (size_t)2 * HH * 128 + b0));
        float4 gn1 = __ldg((const float4*)(gbase + (size_t)2 * HH * 128 + b1));

        u64 acc[3][4];
#pragma unroll
        for (int g = 0; g < 3; g++)
#pragma unroll
            for (int p = 0; p < 4; p++) acc[g][p] = 0ull;

        wait_stage();
        __syncthreads();

#pragma unroll 1
        for (int c = 0; c < 8; c++) {
            if (c < 7) stage_chunk(h_s_u32 + (u32)(((c + 1) & 1) * H_S_BYTES),
                                   hsrc + (c + 1) * CHUNK_K * 128, tid);
            const char* hbuf = h_s + (c & 1) * H_S_BYTES;
            const u64* wk = w_s + (size_t)(c * CHUNK_K) * 24;
#pragma unroll 16
            for (int kk = 0; kk < CHUNK_K; kk++) {
                u64 wr = wk[kk * 24 + j];
                u64 wz = wk[kk * 24 + 8 + j];
                u64 wn = wk[kk * 24 + 16 + j];
                ulonglong2 ha = *(const ulonglong2*)(hbuf + kk * 512 + 16 * q);
                ulonglong2 hb = *(const ulonglong2*)(hbuf + kk * 512 + 256 + 16 * q);
                fma2(acc[0][0], ha.x, wr); fma2(acc[0][1], ha.y, wr);
                fma2(acc[0][2], hb.x, wr); fma2(acc[0][3], hb.y, wr);
                fma2(acc[1][0], ha.x, wz); fma2(acc[1][1], ha.y, wz);
                fma2(acc[1][2], hb.x, wz); fma2(acc[1][3], hb.y, wz);
                fma2(acc[2][0], ha.x, wn); fma2(acc[2][1], ha.y, wn);
                fma2(acc[2][2], hb.x, wn); fma2(acc[2][3], hb.y, wn);
            }
            if (c < 7) { wait_stage(); __syncthreads(); }
        }

        // epilogue: fuse gates for 8 b-values
        float gh[3][8];
#pragma unroll
        for (int g = 0; g < 3; g++)
#pragma unroll
            for (int p = 0; p < 4; p++) {
                float2 f = unpack2(acc[g][p]);
                gh[g][2 * p]     = f.x + bh[g];
                gh[g][2 * p + 1] = f.y + bh[g];
            }
        float gir[8] = {gr0.x, gr0.y, gr0.z, gr0.w, gr1.x, gr1.y, gr1.z, gr1.w};
        float giz[8] = {gz0.x, gz0.y, gz0.z, gz0.w, gz1.x, gz1.y, gz1.z, gz1.w};
        float gin[8] = {gn0.x, gn0.y, gn0.z, gn0.w, gn1.x, gn1.y, gn1.z, gn1.w};
        float hn[8];
#pragma unroll
        for (int e = 0; e < 8; e++) {
            float r = 1.0f / (1.0f + expf(-(gir[e] + gh[0][e])));
            float z = 1.0f / (1.0f + expf(-(giz[e] + gh[1][e])));
            float n = tanhf(gin[e] + r * gh[2][e]);
            hn[e] = (1.0f - z) * n + z * hold[e];
            hold[e] = hn[e];
        }
        __stcg((float4*)&g_h[pw][d][jg][b0], make_float4(hn[0], hn[1], hn[2], hn[3]));
        __stcg((float4*)&g_h[pw][d][jg][b1], make_float4(hn[4], hn[5], hn[6], hn[7]));
        if (WRITE_Y) {
            float* y = g_y0 + ((size_t)t * 1024 + d * HH + jg) * 128;
            *(float4*)(y + b0) = make_float4(hn[0], hn[1], hn[2], hn[3]);
            *(float4*)(y + b1) = make_float4(hn[4], hn[5], hn[6], hn[7]);
        }

        if (t < SQ - 1) {
            __threadfence();
            __syncthreads();
            if (tid == 0) {
                atomicAdd(&g_bar, 1u);
                const unsigned target = (unsigned)(t + 1) * gridDim.x;
                while (*(volatile unsigned*)&g_bar < target) { }
            }
            __syncthreads();
            __threadfence();
        }
    }
}

__global__ void final_kernel(const float* __restrict__ Ws, const float* __restrict__ bs,
                             float* __restrict__ out)
{
    const int b = threadIdx.x;
    float l0 = bs[0], l1 = bs[1];
#pragma unroll 2
    for (int d = 0; d < 2; d++) {
        for (int jj = 0; jj < HH; jj++) {
            float h = g_h[0][d][jj][b];     // 400 steps -> final state in buf 0
            int c = d * HH + jj;
            l0 = fmaf(h, Ws[c], l0);
            l1 = fmaf(h, Ws[1024 + c], l1);
        }
    }
    float m = fmaxf(l0, l1);
    float lse = m + logf(expf(l0 - m) + expf(l1 - m));
    out[b * 2 + 0] = l0 - lse;
    out[b * 2 + 1] = l1 - lse;
}

extern "C" void kernel_launch(void* const* d_in, const int* in_sizes, int n_in,
                              void* d_out, int out_size)
{
    const int*   X    = (const int*)  d_in[0];
    const float* emb  = (const float*)d_in[1];
    const float* Wih0 = (const float*)d_in[2];
    const float* Whh0 = (const float*)d_in[3];
    const float* bih0 = (const float*)d_in[4];
    const float* bhh0 = (const float*)d_in[5];
    const float* Wih1 = (const float*)d_in[6];
    const float* Whh1 = (const float*)d_in[7];
    const float* bih1 = (const float*)d_in[8];
    const float* bhh1 = (const float*)d_in[9];
    const float* Ws   = (const float*)d_in[10];
    const float* bs   = (const float*)d_in[11];
    float* out = (float*)d_out;

    cudaFuncSetAttribute(recur_kernel<true>,  cudaFuncAttributeMaxDynamicSharedMemorySize, RECUR_SMEM);
    cudaFuncSetAttribute(recur_kernel<false>, cudaFuncAttributeMaxDynamicSharedMemorySize, RECUR_SMEM);

    dim3 ggrid(NCOL / 128, SQ);

    init_kernel<<<64, 256>>>();
    gemm_kernel<true><<<ggrid, 256>>>(emb, X, Wih0, bih0, EE);
    recur_kernel<true><<<128, 128, RECUR_SMEM>>>(Whh0, bhh0);

    init_kernel<<<64, 256>>>();
    gemm_kernel<false><<<ggrid, 256>>>(nullptr, nullptr, Wih1, bih1, 1024);
    recur_kernel<false><<<128, 128, RECUR_SMEM>>>(Whh1, bhh1);

    final_kernel<<<1, 128>>>(Ws, bs, out);
}

// round 5
// speedup vs baseline: 1.5170x; 1.5170x over previous
#include <cuda_runtime.h>
#include <cstdint>
#include <math.h>

#define SQ   400
#define BB   128
#define HH   512
#define EE   300
#define G3   1536
#define NCOL 3072

typedef unsigned long long u64;
typedef unsigned int       u32;

__device__ float g_gi[(size_t)SQ * NCOL * BB];      // [t][col(3072)][b(128)]
__device__ float g_y0[(size_t)SQ * 1024 * BB];      // [t][k(1024)][b(128)]
__device__ float g_h[2][2][HH][BB];                 // [buf][dir][k][b]
__device__ unsigned g_bar;

__device__ __forceinline__ void fma2(u64 &d, u64 a, u64 b) {
    asm("fma.rn.f32x2 %0, %1, %2, %0;" : "+l"(d) : "l"(a), "l"(b));
}
__device__ __forceinline__ u64 pack2(float x, float y) {
    u64 r; asm("mov.b64 %0, {%1, %2};" : "=l"(r) : "f"(x), "f"(y)); return r;
}
__device__ __forceinline__ float2 unpack2(u64 v) {
    float2 f;
    f.x = __uint_as_float((unsigned)(v & 0xffffffffull));
    f.y = __uint_as_float((unsigned)(v >> 32));
    return f;
}

__global__ void init_kernel() {
    float* p = &g_h[0][0][0][0];
    size_t n = 2ull * 2 * HH * BB;
    for (size_t i = blockIdx.x * blockDim.x + threadIdx.x; i < n; i += (size_t)gridDim.x * blockDim.x)
        p[i] = 0.0f;
    if (blockIdx.x == 0 && threadIdx.x == 0) g_bar = 0u;
}

// ---------------- big input GEMM (unchanged from passing round 2) ----------------
template <bool GATHER>
__global__ __launch_bounds__(256, 2) void gemm_kernel(
    const float* __restrict__ Aemb, const int* __restrict__ X,
    const float* __restrict__ W, const float* __restrict__ bias, int K)
{
    __shared__ __align__(16) float As[2][8][256];
    __shared__ __align__(16) float Bs[2][8][128];

    const int t     = blockIdx.y;
    const int nbase = blockIdx.x * 128;
    const int tid   = threadIdx.x;
    const int tx    = tid & 15;
    const int ty    = tid >> 4;
    const int lm    = tid >> 1;
    const int lk    = (tid & 1) * 4;
    const int kk8   = tid >> 5;
    const int b0    = (tid & 31) * 4;

    const float* arow;
    if (GATHER) arow = Aemb + (size_t)X[t * 128 + lm] * K;
    else        arow = g_y0 + (size_t)t * 1024 * 128;
    const float* brow = W + (size_t)(nbase + lm) * K;

    u64 acc[8][4];
#pragma unroll
    for (int r = 0; r < 8; r++)
#pragma unroll
        for (int c = 0; c < 4; c++) acc[r][c] = 0ull;

    const int nk = (K + 7) >> 3;

    float4 a4, b4;
    if (GATHER) a4 = (lk < K) ? *(const float4*)(arow + lk) : make_float4(0,0,0,0);
    else        a4 = *(const float4*)(arow + (size_t)kk8 * 128 + b0);
    b4 = (lk < K) ? *(const float4*)(brow + lk) : make_float4(0,0,0,0);

    for (int it = 0; it < nk; it++) {
        const int buf = it & 1;
#pragma unroll
        for (int i = 0; i < 4; i++) {
            float va = (&a4.x)[i];
            if (GATHER) *(u64*)&As[buf][lk + i][2 * lm] = pack2(va, va);
            else        *(u64*)&As[buf][kk8][2 * (b0 + i)] = pack2(va, va);
            Bs[buf][lk + i][lm] = (&b4.x)[i];
        }
        __syncthreads();
        if (it + 1 < nk) {
            int kn = (it + 1) * 8 + lk;
            if (GATHER) a4 = (kn < K) ? *(const float4*)(arow + kn) : make_float4(0,0,0,0);
            else        a4 = *(const float4*)(arow + ((size_t)(it + 1) * 8 + kk8) * 128 + b0);
            b4 = (kn < K) ? *(const float4*)(brow + kn) : make_float4(0,0,0,0);
        }
#pragma unroll
        for (int kk = 0; kk < 8; kk++) {
            u64 ad[8];
#pragma unroll
            for (int r2 = 0; r2 < 4; r2++) {
                ulonglong2 aa = *(const ulonglong2*)&As[buf][kk][ty * 16 + r2 * 4];
                ad[2 * r2] = aa.x; ad[2 * r2 + 1] = aa.y;
            }
            u64 bp[4];
#pragma unroll
            for (int c2 = 0; c2 < 2; c2++) {
                ulonglong2 bv = *(const ulonglong2*)&Bs[buf][kk][tx * 8 + c2 * 4];
                bp[2 * c2] = bv.x; bp[2 * c2 + 1] = bv.y;
            }
#pragma unroll
            for (int r = 0; r < 8; r++)
#pragma unroll
                for (int c = 0; c < 4; c++) fma2(acc[r][c], ad[r], bp[c]);
        }
        __syncthreads();
    }

    float* cbase = g_gi + ((size_t)t * NCOL + nbase + tx * 8) * 128 + ty * 8;
#pragma unroll
    for (int c = 0; c < 8; c++) {
        float bv = bias[nbase + tx * 8 + c];
        float v[8];
#pragma unroll
        for (int r = 0; r < 8; r++) {
            float2 f = unpack2(acc[r][c >> 1]);
            v[r] = ((c & 1) ? f.y : f.x) + bv;
        }
        float4* dst = (float4*)(cbase + (size_t)c * 128);
        dst[0] = make_float4(v[0], v[1], v[2], v[3]);
        dst[1] = make_float4(v[4], v[5], v[6], v[7]);
    }
}

// ---------------- persistent recurrence: 256 thr, smem-staged h ----------------
// 128 CTAs: dir = cta>>6, jbase = (cta&63)*8.
// 256 threads: j = tid>>5 (0..7, one j per warp), lane = tid&31 -> b quad 4*lane.
// Per thread: 3 gates x 2 b-pairs = 6 u64 accs.  No duplication of (j,b) work.
#define CHUNK_K 64
#define W_S_BYTES (512 * 24 * 8)
#define H_S_BYTES (CHUNK_K * 128 * 4)
#define RECUR_SMEM (W_S_BYTES + 2 * H_S_BYTES)

__device__ __forceinline__ void stage_chunk(u32 sdst, const float* src, int tid) {
#pragma unroll
    for (int i = 0; i < 8; i++) {
        asm volatile("cp.async.cg.shared.global [%0], [%1], 16;"
                     :: "r"(sdst + (u32)(tid * 16 + i * 4096)),
                        "l"(src + tid * 4 + i * 1024) : "memory");
    }
    asm volatile("cp.async.commit_group;" ::: "memory");
}
__device__ __forceinline__ void wait_stage() {
    asm volatile("cp.async.wait_group 0;" ::: "memory");
}

template <bool WRITE_Y>
__global__ __launch_bounds__(256, 1) void recur_kernel(
    const float* __restrict__ Whh, const float* __restrict__ bhh)
{
    extern __shared__ __align__(16) char smem_raw[];
    u64*   w_s = (u64*)smem_raw;                       // [k][24] dup weight pairs
    char*  h_s = smem_raw + W_S_BYTES;                 // 2 x [64][128] floats
    u32 h_s_u32 = (u32)__cvta_generic_to_shared(h_s);

    const int cta   = blockIdx.x;
    const int d     = cta >> 6;
    const int jbase = (cta & 63) * 8;
    const int tid   = threadIdx.x;
    const int j     = tid >> 5;
    const int lane  = tid & 31;
    const int jg    = jbase + j;
    const int b0    = 4 * lane;

    // fill duplicated weight pairs: w_s[k*24 + g*8 + jj] = (w,w)
    for (int idx = tid; idx < 512 * 24; idx += 256) {
        int r = idx >> 9, k = idx & 511;
        int g = r >> 3, jj = r & 7;
        float v = Whh[((size_t)d * G3 + g * HH + jbase + jj) * HH + k];
        w_s[(size_t)k * 24 + r] = pack2(v, v);
    }
    float bh[3];
#pragma unroll
    for (int g = 0; g < 3; g++) bh[g] = bhh[(size_t)d * G3 + g * HH + jg];
    __syncthreads();

    float hold[4];
#pragma unroll
    for (int e = 0; e < 4; e++) hold[e] = 0.0f;

    for (int t = 0; t < SQ; t++) {
        const int pr = t & 1, pw = pr ^ 1;
        const float* hsrc = &g_h[pr][d][0][0];

        stage_chunk(h_s_u32, hsrc, tid);

        const float* gbase = g_gi + (size_t)t * NCOL * 128 + (size_t)(d * G3 + jg) * 128;
        float4 gr = __ldg((const float4*)(gbase + b0));
        float4 gz = __ldg((const float4*)(gbase + (size_t)HH * 128 + b0));
        float4 gn = __ldg((const float4*)(gbase + (size_t)2 * HH * 128 + b0));

        u64 acc[3][2];
#pragma unroll
        for (int g = 0; g < 3; g++) { acc[g][0] = 0ull; acc[g][1] = 0ull; }

        wait_stage();
        __syncthreads();

#pragma unroll 1
        for (int c = 0; c < 8; c++) {
            if (c < 7) stage_chunk(h_s_u32 + (u32)(((c + 1) & 1) * H_S_BYTES),
                                   hsrc + (c + 1) * CHUNK_K * 128, tid);
            const char* hbuf = h_s + (c & 1) * H_S_BYTES;
            const u64* wk = w_s + (size_t)(c * CHUNK_K) * 24;
#pragma unroll 8
            for (int kk = 0; kk < CHUNK_K; kk++) {
                u64 wr = wk[kk * 24 + j];
                u64 wz = wk[kk * 24 + 8 + j];
                u64 wn = wk[kk * 24 + 16 + j];
                ulonglong2 hq = *(const ulonglong2*)(hbuf + kk * 512 + 16 * lane);
                fma2(acc[0][0], hq.x, wr); fma2(acc[0][1], hq.y, wr);
                fma2(acc[1][0], hq.x, wz); fma2(acc[1][1], hq.y, wz);
                fma2(acc[2][0], hq.x, wn); fma2(acc[2][1], hq.y, wn);
            }
            if (c < 7) { wait_stage(); __syncthreads(); }
        }

        // epilogue: fuse gates for 4 b-values
        float gh[3][4];
#pragma unroll
        for (int g = 0; g < 3; g++) {
            float2 f0 = unpack2(acc[g][0]);
            float2 f1 = unpack2(acc[g][1]);
            gh[g][0] = f0.x + bh[g]; gh[g][1] = f0.y + bh[g];
            gh[g][2] = f1.x + bh[g]; gh[g][3] = f1.y + bh[g];
        }
        float gir[4] = {gr.x, gr.y, gr.z, gr.w};
        float giz[4] = {gz.x, gz.y, gz.z, gz.w};
        float gin[4] = {gn.x, gn.y, gn.z, gn.w};
        float hn[4];
#pragma unroll
        for (int e = 0; e < 4; e++) {
            float r = 1.0f / (1.0f + expf(-(gir[e] + gh[0][e])));
            float z = 1.0f / (1.0f + expf(-(giz[e] + gh[1][e])));
            float n = tanhf(gin[e] + r * gh[2][e]);
            hn[e] = (1.0f - z) * n + z * hold[e];
            hold[e] = hn[e];
        }
        __stcg((float4*)&g_h[pw][d][jg][b0], make_float4(hn[0], hn[1], hn[2], hn[3]));
        if (WRITE_Y) {
            float* y = g_y0 + ((size_t)t * 1024 + d * HH + jg) * 128;
            *(float4*)(y + b0) = make_float4(hn[0], hn[1], hn[2], hn[3]);
        }

        if (t < SQ - 1) {
            __threadfence();
            __syncthreads();
            if (tid == 0) {
                atomicAdd(&g_bar, 1u);
                const unsigned target = (unsigned)(t + 1) * gridDim.x;
                while (*(volatile unsigned*)&g_bar < target) { }
            }
            __syncthreads();
            __threadfence();
        }
    }
}

__global__ void final_kernel(const float* __restrict__ Ws, const float* __restrict__ bs,
                             float* __restrict__ out)
{
    const int b = threadIdx.x;
    float l0 = bs[0], l1 = bs[1];
#pragma unroll 2
    for (int d = 0; d < 2; d++) {
        for (int jj = 0; jj < HH; jj++) {
            float h = g_h[0][d][jj][b];     // 400 steps -> final state in buf 0
            int c = d * HH + jj;
            l0 = fmaf(h, Ws[c], l0);
            l1 = fmaf(h, Ws[1024 + c], l1);
        }
    }
    float m = fmaxf(l0, l1);
    float lse = m + logf(expf(l0 - m) + expf(l1 - m));
    out[b * 2 + 0] = l0 - lse;
    out[b * 2 + 1] = l1 - lse;
}

extern "C" void kernel_launch(void* const* d_in, const int* in_sizes, int n_in,
                              void* d_out, int out_size)
{
    const int*   X    = (const int*)  d_in[0];
    const float* emb  = (const float*)d_in[1];
    const float* Wih0 = (const float*)d_in[2];
    const float* Whh0 = (const float*)d_in[3];
    const float* bih0 = (const float*)d_in[4];
    const float* bhh0 = (const float*)d_in[5];
    const float* Wih1 = (const float*)d_in[6];
    const float* Whh1 = (const float*)d_in[7];
    const float* bih1 = (const float*)d_in[8];
    const float* bhh1 = (const float*)d_in[9];
    const float* Ws   = (const float*)d_in[10];
    const float* bs   = (const float*)d_in[11];
    float* out = (float*)d_out;

    cudaFuncSetAttribute(recur_kernel<true>,  cudaFuncAttributeMaxDynamicSharedMemorySize, RECUR_SMEM);
    cudaFuncSetAttribute(recur_kernel<false>, cudaFuncAttributeMaxDynamicSharedMemorySize, RECUR_SMEM);

    dim3 ggrid(NCOL / 128, SQ);

    init_kernel<<<64, 256>>>();
    gemm_kernel<true><<<ggrid, 256>>>(emb, X, Wih0, bih0, EE);
    recur_kernel<true><<<128, 256, RECUR_SMEM>>>(Whh0, bhh0);

    init_kernel<<<64, 256>>>();
    gemm_kernel<false><<<ggrid, 256>>>(nullptr, nullptr, Wih1, bih1, 1024);
    recur_kernel<false><<<128, 256, RECUR_SMEM>>>(Whh1, bhh1);

    final_kernel<<<1, 128>>>(Ws, bs, out);
}

// round 7
// speedup vs baseline: 1.9042x; 1.2552x over previous
#include <cuda_runtime.h>
#include <cuda_bf16.h>
#include <cstdint>
#include <math.h>

#define SQ   400
#define BB   128
#define HH   512
#define EE   300
#define G3   1536
#define NCOL 3072

typedef unsigned long long u64;
typedef unsigned int       u32;

__device__ float g_gi[(size_t)SQ * NCOL * BB];           // [t][col(3072)][b(128)]
__device__ __nv_bfloat16 g_y0h[(size_t)SQ * BB * 1024];  // [t][b][k] hi plane
__device__ __nv_bfloat16 g_y0l[(size_t)SQ * BB * 1024];  // [t][b][k] lo plane
__device__ __nv_bfloat16 g_wh[(size_t)NCOL * 1024];      // W hi plane [col][Kpad]
__device__ __nv_bfloat16 g_wl[(size_t)NCOL * 1024];      // W lo plane
__device__ float g_h[2][2][HH][BB];                      // [buf][dir][k][b]
__device__ unsigned g_bar;

__device__ __forceinline__ void fma2(u64 &d, u64 a, u64 b) {
    asm("fma.rn.f32x2 %0, %1, %2, %0;" : "+l"(d) : "l"(a), "l"(b));
}
__device__ __forceinline__ u64 pack2(float x, float y) {
    u64 r; asm("mov.b64 %0, {%1, %2};" : "=l"(r) : "f"(x), "f"(y)); return r;
}
__device__ __forceinline__ float2 unpack2(u64 v) {
    float2 f;
    f.x = __uint_as_float((unsigned)(v & 0xffffffffull));
    f.y = __uint_as_float((unsigned)(v >> 32));
    return f;
}

__global__ void init_kernel() {
    float* p = &g_h[0][0][0][0];
    size_t n = 2ull * 2 * HH * BB;
    for (size_t i = blockIdx.x * blockDim.x + threadIdx.x; i < n; i += (size_t)gridDim.x * blockDim.x)
        p[i] = 0.0f;
    if (blockIdx.x == 0 && threadIdx.x == 0) g_bar = 0u;
}

// split W fp32 [3072][K] -> hi/lo bf16 planes [3072][Kpad], zero-padded
__global__ void wsplit_kernel(const float* __restrict__ W, int K, int Kpad) {
    size_t n = (size_t)NCOL * Kpad;
    for (size_t i = blockIdx.x * blockDim.x + threadIdx.x; i < n; i += (size_t)gridDim.x * blockDim.x) {
        int col = (int)(i / Kpad), k = (int)(i % Kpad);
        float v = (k < K) ? W[(size_t)col * K + k] : 0.0f;
        __nv_bfloat16 h = __float2bfloat16(v);
        g_wh[i] = h;
        g_wl[i] = __float2bfloat16(v - __bfloat162float(h));
    }
}

// ================= HMMA bf16-split GEMM =================
// D[col 128][b 128] = sum_k W[col][k] * act[b][k], fp32 accum.
// 8 warps: wm = wid&3 (32 M-rows), wn = wid>>2 (64 N-cols).
#define PITCH 144                 // bytes per smem tile row (64 bf16 + 8 pad)
#define TILE_B (128 * PITCH)      // 18432
#define BUFB   (4 * TILE_B)       // Ah, Al, Bh, Bl
#define GEMM_SMEM (2 * BUFB)      // 147456

__device__ __forceinline__ void cpa16(u32 dst, const void* src) {
    asm volatile("cp.async.cg.shared.global [%0], [%1], 16;" :: "r"(dst), "l"(src) : "memory");
}
__device__ __forceinline__ void ldsm4(u32 &r0, u32 &r1, u32 &r2, u32 &r3, u32 addr) {
    asm volatile("ldmatrix.sync.aligned.m8n8.x4.shared.b16 {%0,%1,%2,%3}, [%4];"
                 : "=r"(r0), "=r"(r1), "=r"(r2), "=r"(r3) : "r"(addr));
}
__device__ __forceinline__ void mma16816(float* c, const u32* a, u32 b0, u32 b1) {
    asm volatile("mma.sync.aligned.m16n8k16.row.col.f32.bf16.bf16.f32 "
                 "{%0,%1,%2,%3}, {%4,%5,%6,%7}, {%8,%9}, {%0,%1,%2,%3};"
                 : "+f"(c[0]), "+f"(c[1]), "+f"(c[2]), "+f"(c[3])
                 : "r"(a[0]), "r"(a[1]), "r"(a[2]), "r"(a[3]), "r"(b0), "r"(b1));
}

template <bool GATHER>
__global__ __launch_bounds__(256, 1)
void gemm_tc(const float* __restrict__ emb, const int* __restrict__ X,
             const float* __restrict__ bias, int Kpad, int nch)
{
    extern __shared__ __align__(16) char sm[];
    const u32 smb = (u32)__cvta_generic_to_shared(sm);

    const int t     = blockIdx.y;
    const int nbase = blockIdx.x * 128;
    const int tid   = threadIdx.x;
    const int wid   = tid >> 5;
    const int lane  = tid & 31;
    const int row   = tid >> 1;      // 0..127 (copy row)
    const int sub   = tid & 1;       // k half
    const int wm    = wid & 3;
    const int wn    = wid >> 2;

    const float* brow_f = GATHER ? emb + (size_t)X[t * 128 + row] * EE : nullptr;

    float acc[2][8][4];
#pragma unroll
    for (int mt = 0; mt < 2; mt++)
#pragma unroll
        for (int j = 0; j < 8; j++)
#pragma unroll
            for (int e = 0; e < 4; e++) acc[mt][j][e] = 0.0f;

    // precomputed ldmatrix offsets (bytes within a tile)
    u32 aoff[2], boff[4];
#pragma unroll
    for (int mt = 0; mt < 2; mt++)
        aoff[mt] = (u32)((wm * 32 + mt * 16 + (lane & 15)) * PITCH + (lane >> 4) * 16);
#pragma unroll
    for (int nt = 0; nt < 4; nt++)
        boff[nt] = (u32)((wn * 64 + nt * 16 + (lane & 7) + ((lane >> 3) & 1) * 8) * PITCH
                         + (lane >> 4) * 16);

    // ---- chunk issue ----
    auto issue = [&](int c) {
        const u32 tb = smb + (u32)((c & 1) * BUFB);
        const int k0 = c * 64;
        const __nv_bfloat16* ah = g_wh + (size_t)(nbase + row) * Kpad + k0 + sub * 32;
        const __nv_bfloat16* al = g_wl + (size_t)(nbase + row) * Kpad + k0 + sub * 32;
#pragma unroll
        for (int i = 0; i < 4; i++) {
            u32 so = (u32)(row * PITCH + sub * 64 + i * 16);
            cpa16(tb + so, ah + i * 8);
            cpa16(tb + TILE_B + so, al + i * 8);
        }
        if (!GATHER) {
            const __nv_bfloat16* bh = g_y0h + ((size_t)t * 128 + row) * 1024 + k0 + sub * 32;
            const __nv_bfloat16* bl = g_y0l + ((size_t)t * 128 + row) * 1024 + k0 + sub * 32;
#pragma unroll
            for (int i = 0; i < 4; i++) {
                u32 so = (u32)(row * PITCH + sub * 64 + i * 16);
                cpa16(tb + 2 * TILE_B + so, bh + i * 8);
                cpa16(tb + 3 * TILE_B + so, bl + i * 8);
            }
        } else {
            char* buf = sm + (c & 1) * BUFB;
#pragma unroll
            for (int i = 0; i < 8; i++) {
                int k = k0 + sub * 32 + i * 4;
                float4 v = (k + 4 <= EE) ? *(const float4*)(brow_f + k) : make_float4(0, 0, 0, 0);
                u64 ph = 0, pl = 0;
#pragma unroll
                for (int jx = 0; jx < 4; jx++) {
                    float f = (&v.x)[jx];
                    __nv_bfloat16 hb = __float2bfloat16(f);
                    __nv_bfloat16 lb = __float2bfloat16(f - __bfloat162float(hb));
                    ph |= (u64)__bfloat16_as_ushort(hb) << (16 * jx);
                    pl |= (u64)__bfloat16_as_ushort(lb) << (16 * jx);
                }
                u32 so = (u32)(row * PITCH + sub * 64 + i * 8);
                *(u64*)(buf + 2 * TILE_B + so) = ph;
                *(u64*)(buf + 3 * TILE_B + so) = pl;
            }
        }
        asm volatile("cp.async.commit_group;" ::: "memory");
    };

    issue(0);
    for (int c = 0; c < nch; c++) {
        if (c + 1 < nch) {
            issue(c + 1);
            asm volatile("cp.async.wait_group 1;" ::: "memory");
        } else {
            asm volatile("cp.async.wait_group 0;" ::: "memory");
        }
        __syncthreads();

        const u32 tb = smb + (u32)((c & 1) * BUFB);
#pragma unroll
        for (int ks = 0; ks < 4; ks++) {
            const u32 kb = (u32)(ks * 32);
            u32 ah[2][4], al[2][4], bh[4][4], bl[4][4];
#pragma unroll
            for (int mt = 0; mt < 2; mt++) {
                ldsm4(ah[mt][0], ah[mt][1], ah[mt][2], ah[mt][3], tb + aoff[mt] + kb);
                ldsm4(al[mt][0], al[mt][1], al[mt][2], al[mt][3], tb + TILE_B + aoff[mt] + kb);
            }
#pragma unroll
            for (int nt = 0; nt < 4; nt++) {
                ldsm4(bh[nt][0], bh[nt][1], bh[nt][2], bh[nt][3], tb + 2 * TILE_B + boff[nt] + kb);
                ldsm4(bl[nt][0], bl[nt][1], bl[nt][2], bl[nt][3], tb + 3 * TILE_B + boff[nt] + kb);
            }
#pragma unroll
            for (int mt = 0; mt < 2; mt++)
#pragma unroll
                for (int nt = 0; nt < 4; nt++)
#pragma unroll
                    for (int hf = 0; hf < 2; hf++) {
                        float* cc = acc[mt][nt * 2 + hf];
                        mma16816(cc, ah[mt], bh[nt][hf], bh[nt][hf + 2]);   // Ah*Bh
                        mma16816(cc, ah[mt], bl[nt][hf], bl[nt][hf + 2]);   // Ah*Bl
                        mma16816(cc, al[mt], bh[nt][hf], bh[nt][hf + 2]);   // Al*Bh
                    }
        }
        __syncthreads();
    }

    // epilogue: add bias, store D[col][b] -> g_gi[t][col][b]
#pragma unroll
    for (int mt = 0; mt < 2; mt++) {
        const int m0 = wm * 32 + mt * 16 + (lane >> 2);
        const int m1 = m0 + 8;
        const float bv0 = bias[nbase + m0];
        const float bv1 = bias[nbase + m1];
        float* d0 = g_gi + ((size_t)t * NCOL + nbase + m0) * 128;
        float* d1 = g_gi + ((size_t)t * NCOL + nbase + m1) * 128;
#pragma unroll
        for (int j = 0; j < 8; j++) {
            const int b = wn * 64 + j * 8 + (lane & 3) * 2;
            *(float2*)(d0 + b) = make_float2(acc[mt][j][0] + bv0, acc[mt][j][1] + bv0);
            *(float2*)(d1 + b) = make_float2(acc[mt][j][2] + bv1, acc[mt][j][3] + bv1);
        }
    }
}

// ================= persistent recurrence (round-5 proven) =================
#define CHUNK_K 64
#define W_S_BYTES (512 * 24 * 8)
#define H_S_BYTES (CHUNK_K * 128 * 4)
#define Y_S_BYTES (8 * 128 * 4)
#define RECUR_SMEM (W_S_BYTES + 2 * H_S_BYTES + Y_S_BYTES)

__device__ __forceinline__ void stage_chunk(u32 sdst, const float* src, int tid) {
#pragma unroll
    for (int i = 0; i < 8; i++) {
        asm volatile("cp.async.cg.shared.global [%0], [%1], 16;"
                     :: "r"(sdst + (u32)(tid * 16 + i * 4096)),
                        "l"(src + tid * 4 + i * 1024) : "memory");
    }
    asm volatile("cp.async.commit_group;" ::: "memory");
}
__device__ __forceinline__ void wait_stage() {
    asm volatile("cp.async.wait_group 0;" ::: "memory");
}

template <bool WRITE_Y>
__global__ __launch_bounds__(256, 1) void recur_kernel(
    const float* __restrict__ Whh, const float* __restrict__ bhh)
{
    extern __shared__ __align__(16) char smem_raw[];
    u64*   w_s = (u64*)smem_raw;
    char*  h_s = smem_raw + W_S_BYTES;
    float* y_s = (float*)(smem_raw + W_S_BYTES + 2 * H_S_BYTES);
    u32 h_s_u32 = (u32)__cvta_generic_to_shared(h_s);

    const int cta   = blockIdx.x;
    const int d     = cta >> 6;
    const int jbase = (cta & 63) * 8;
    const int tid   = threadIdx.x;
    const int j     = tid >> 5;
    const int lane  = tid & 31;
    const int jg    = jbase + j;
    const int b0    = 4 * lane;

    for (int idx = tid; idx < 512 * 24; idx += 256) {
        int r = idx >> 9, k = idx & 511;
        int g = r >> 3, jj = r & 7;
        float v = Whh[((size_t)d * G3 + g * HH + jbase + jj) * HH + k];
        w_s[(size_t)k * 24 + r] = pack2(v, v);
    }
    float bh[3];
#pragma unroll
    for (int g = 0; g < 3; g++) bh[g] = bhh[(size_t)d * G3 + g * HH + jg];
    __syncthreads();

    float hold[4];
#pragma unroll
    for (int e = 0; e < 4; e++) hold[e] = 0.0f;

    for (int t = 0; t < SQ; t++) {
        const int pr = t & 1, pw = pr ^ 1;
        const float* hsrc = &g_h[pr][d][0][0];

        stage_chunk(h_s_u32, hsrc, tid);

        const float* gbase = g_gi + (size_t)t * NCOL * 128 + (size_t)(d * G3 + jg) * 128;
        float4 gr = __ldg((const float4*)(gbase + b0));
        float4 gz = __ldg((const float4*)(gbase + (size_t)HH * 128 + b0));
        float4 gn = __ldg((const float4*)(gbase + (size_t)2 * HH * 128 + b0));

        u64 acc[3][2];
#pragma unroll
        for (int g = 0; g < 3; g++) { acc[g][0] = 0ull; acc[g][1] = 0ull; }

        wait_stage();
        __syncthreads();

#pragma unroll 1
        for (int c = 0; c < 8; c++) {
            if (c < 7) stage_chunk(h_s_u32 + (u32)(((c + 1) & 1) * H_S_BYTES),
                                   hsrc + (c + 1) * CHUNK_K * 128, tid);
            const char* hbuf = h_s + (c & 1) * H_S_BYTES;
            const u64* wk = w_s + (size_t)(c * CHUNK_K) * 24;
#pragma unroll 8
            for (int kk = 0; kk < CHUNK_K; kk++) {
                u64 wr = wk[kk * 24 + j];
                u64 wz = wk[kk * 24 + 8 + j];
                u64 wn = wk[kk * 24 + 16 + j];
                ulonglong2 hq = *(const ulonglong2*)(hbuf + kk * 512 + 16 * lane);
                fma2(acc[0][0], hq.x, wr); fma2(acc[0][1], hq.y, wr);
                fma2(acc[1][0], hq.x, wz); fma2(acc[1][1], hq.y, wz);
                fma2(acc[2][0], hq.x, wn); fma2(acc[2][1], hq.y, wn);
            }
            if (c < 7) { wait_stage(); __syncthreads(); }
        }

        float gh[3][4];
#pragma unroll
        for (int g = 0; g < 3; g++) {
            float2 f0 = unpack2(acc[g][0]);
            float2 f1 = unpack2(acc[g][1]);
            gh[g][0] = f0.x + bh[g]; gh[g][1] = f0.y + bh[g];
            gh[g][2] = f1.x + bh[g]; gh[g][3] = f1.y + bh[g];
        }
        float gir[4] = {gr.x, gr.y, gr.z, gr.w};
        float giz[4] = {gz.x, gz.y, gz.z, gz.w};
        float gin[4] = {gn.x, gn.y, gn.z, gn.w};
        float hn[4];
#pragma unroll
        for (int e = 0; e < 4; e++) {
            float r = 1.0f / (1.0f + expf(-(gir[e] + gh[0][e])));
            float z = 1.0f / (1.0f + expf(-(giz[e] + gh[1][e])));
            float n = tanhf(gin[e] + r * gh[2][e]);
            hn[e] = (1.0f - z) * n + z * hold[e];
            hold[e] = hn[e];
        }
        __stcg((float4*)&g_h[pw][d][jg][b0], make_float4(hn[0], hn[1], hn[2], hn[3]));

        if (WRITE_Y) {
            *(float4*)(y_s + j * 128 + b0) = make_float4(hn[0], hn[1], hn[2], hn[3]);
            __syncthreads();
            if (tid < 128) {
                const int b = tid;
                u32 ph[4], pl[4];
#pragma unroll
                for (int p = 0; p < 4; p++) {
                    float v0 = y_s[(2 * p) * 128 + b];
                    float v1 = y_s[(2 * p + 1) * 128 + b];
                    __nv_bfloat16 h0 = __float2bfloat16(v0);
                    __nv_bfloat16 h1 = __float2bfloat16(v1);
                    __nv_bfloat16 l0 = __float2bfloat16(v0 - __bfloat162float(h0));
                    __nv_bfloat16 l1 = __float2bfloat16(v1 - __bfloat162float(h1));
                    ph[p] = (u32)__bfloat16_as_ushort(h0) | ((u32)__bfloat16_as_ushort(h1) << 16);
                    pl[p] = (u32)__bfloat16_as_ushort(l0) | ((u32)__bfloat16_as_ushort(l1) << 16);
                }
                size_t yo = ((size_t)t * 128 + b) * 1024 + d * HH + jbase;
                *(uint4*)(g_y0h + yo) = make_uint4(ph[0], ph[1], ph[2], ph[3]);
                *(uint4*)(g_y0l + yo) = make_uint4(pl[0], pl[1], pl[2], pl[3]);
            }
        }

        if (t < SQ - 1) {
            __threadfence();
            __syncthreads();
            if (tid == 0) {
                atomicAdd(&g_bar, 1u);
                const unsigned target = (unsigned)(t + 1) * gridDim.x;
                while (*(volatile unsigned*)&g_bar < target) { }
            }
            __syncthreads();
            __threadfence();
        }
    }
}

__global__ void final_kernel(const float* __restrict__ Ws, const float* __restrict__ bs,
                             float* __restrict__ out)
{
    const int b = threadIdx.x;
    float l0 = bs[0], l1 = bs[1];
#pragma unroll 2
    for (int d = 0; d < 2; d++) {
        for (int jj = 0; jj < HH; jj++) {
            float h = g_h[0][d][jj][b];
            int c = d * HH + jj;
            l0 = fmaf(h, Ws[c], l0);
            l1 = fmaf(h, Ws[1024 + c], l1);
        }
    }
    float m = fmaxf(l0, l1);
    float lse = m + logf(expf(l0 - m) + expf(l1 - m));
    out[b * 2 + 0] = l0 - lse;
    out[b * 2 + 1] = l1 - lse;
}

extern "C" void kernel_launch(void* const* d_in, const int* in_sizes, int n_in,
                              void* d_out, int out_size)
{
    const int*   X    = (const int*)  d_in[0];
    const float* emb  = (const float*)d_in[1];
    const float* Wih0 = (const float*)d_in[2];
    const float* Whh0 = (const float*)d_in[3];
    const float* bih0 = (const float*)d_in[4];
    const float* bhh0 = (const float*)d_in[5];
    const float* Wih1 = (const float*)d_in[6];
    const float* Whh1 = (const float*)d_in[7];
    const float* bih1 = (const float*)d_in[8];
    const float* bhh1 = (const float*)d_in[9];
    const float* Ws   = (const float*)d_in[10];
    const float* bs   = (const float*)d_in[11];
    float* out = (float*)d_out;

    cudaFuncSetAttribute(recur_kernel<true>,  cudaFuncAttributeMaxDynamicSharedMemorySize, RECUR_SMEM);
    cudaFuncSetAttribute(recur_kernel<false>, cudaFuncAttributeMaxDynamicSharedMemorySize, RECUR_SMEM);
    cudaFuncSetAttribute(gemm_tc<true>,  cudaFuncAttributeMaxDynamicSharedMemorySize, GEMM_SMEM);
    cudaFuncSetAttribute(gemm_tc<false>, cudaFuncAttributeMaxDynamicSharedMemorySize, GEMM_SMEM);

    dim3 ggrid(NCOL / 128, SQ);

    // layer 0
    init_kernel<<<64, 256>>>();
    wsplit_kernel<<<480, 256>>>(Wih0, EE, 320);
    gemm_tc<true><<<ggrid, 256, GEMM_SMEM>>>(emb, X, bih0, 320, 5);
    recur_kernel<true><<<128, 256, RECUR_SMEM>>>(Whh0, bhh0);

    // layer 1
    init_kernel<<<64, 256>>>();
    wsplit_kernel<<<480, 256>>>(Wih1, 1024, 1024);
    gemm_tc<false><<<ggrid, 256, GEMM_SMEM>>>(nullptr, nullptr, bih1, 1024, 16);
    recur_kernel<false><<<128, 256, RECUR_SMEM>>>(Whh1, bhh1);

    final_kernel<<<1, 128>>>(Ws, bs, out);
}

// round 8
// speedup vs baseline: 2.2052x; 1.1581x over previous
#include <cuda_runtime.h>
#include <cuda_bf16.h>
#include <cstdint>
#include <math.h>

#define SQ   400
#define BB   128
#define HH   512
#define EE   300
#define G3   1536
#define NCOL 3072

typedef unsigned long long u64;
typedef unsigned int       u32;

__device__ float g_gi[(size_t)SQ * NCOL * BB];           // [t][col(3072)][b(128)]
__device__ __nv_bfloat16 g_y0h[(size_t)SQ * BB * 1024];  // [t][b][k] hi plane
__device__ __nv_bfloat16 g_y0l[(size_t)SQ * BB * 1024];  // [t][b][k] lo plane
__device__ __nv_bfloat16 g_wh[(size_t)NCOL * 1024];      // W hi plane [col][Kpad]
__device__ __nv_bfloat16 g_wl[(size_t)NCOL * 1024];      // W lo plane
__device__ __nv_bfloat16 g_hbh[2][2][BB][HH];            // [buf][dir][b][k] h hi
__device__ __nv_bfloat16 g_hbl[2][2][BB][HH];            // [buf][dir][b][k] h lo
__device__ unsigned g_bar;

__device__ __forceinline__ u64 pack2(float x, float y) {
    u64 r; asm("mov.b64 %0, {%1, %2};" : "=l"(r) : "f"(x), "f"(y)); return r;
}

__global__ void init_kernel() {
    __nv_bfloat16* p0 = &g_hbh[0][0][0][0];
    __nv_bfloat16* p1 = &g_hbl[0][0][0][0];
    size_t n = 2ull * 2 * BB * HH;
    for (size_t i = blockIdx.x * blockDim.x + threadIdx.x; i < n; i += (size_t)gridDim.x * blockDim.x) {
        p0[i] = __float2bfloat16(0.0f);
        p1[i] = __float2bfloat16(0.0f);
    }
    if (blockIdx.x == 0 && threadIdx.x == 0) g_bar = 0u;
}

// split W fp32 [3072][K] -> hi/lo bf16 planes [3072][Kpad], zero-padded
__global__ void wsplit_kernel(const float* __restrict__ W, int K, int Kpad) {
    size_t n = (size_t)NCOL * Kpad;
    for (size_t i = blockIdx.x * blockDim.x + threadIdx.x; i < n; i += (size_t)gridDim.x * blockDim.x) {
        int col = (int)(i / Kpad), k = (int)(i % Kpad);
        float v = (k < K) ? W[(size_t)col * K + k] : 0.0f;
        __nv_bfloat16 h = __float2bfloat16(v);
        g_wh[i] = h;
        g_wl[i] = __float2bfloat16(v - __bfloat162float(h));
    }
}

// ---------------- common HMMA helpers ----------------
__device__ __forceinline__ void cpa16(u32 dst, const void* src) {
    asm volatile("cp.async.cg.shared.global [%0], [%1], 16;" :: "r"(dst), "l"(src) : "memory");
}
__device__ __forceinline__ void ldsm4(u32 &r0, u32 &r1, u32 &r2, u32 &r3, u32 addr) {
    asm volatile("ldmatrix.sync.aligned.m8n8.x4.shared.b16 {%0,%1,%2,%3}, [%4];"
                 : "=r"(r0), "=r"(r1), "=r"(r2), "=r"(r3) : "r"(addr));
}
__device__ __forceinline__ void mma16816(float* c, const u32* a, u32 b0, u32 b1) {
    asm volatile("mma.sync.aligned.m16n8k16.row.col.f32.bf16.bf16.f32 "
                 "{%0,%1,%2,%3}, {%4,%5,%6,%7}, {%8,%9}, {%0,%1,%2,%3};"
                 : "+f"(c[0]), "+f"(c[1]), "+f"(c[2]), "+f"(c[3])
                 : "r"(a[0]), "r"(a[1]), "r"(a[2]), "r"(a[3]), "r"(b0), "r"(b1));
}

// ================= HMMA bf16-split input GEMM (round-7 proven) =================
#define PITCH 144
#define TILE_B (128 * PITCH)
#define BUFB   (4 * TILE_B)
#define GEMM_SMEM (2 * BUFB)

template <bool GATHER>
__global__ __launch_bounds__(256, 1)
void gemm_tc(const float* __restrict__ emb, const int* __restrict__ X,
             const float* __restrict__ bias, int Kpad, int nch)
{
    extern __shared__ __align__(16) char sm[];
    const u32 smb = (u32)__cvta_generic_to_shared(sm);

    const int t     = blockIdx.y;
    const int nbase = blockIdx.x * 128;
    const int tid   = threadIdx.x;
    const int wid   = tid >> 5;
    const int lane  = tid & 31;
    const int row   = tid >> 1;
    const int sub   = tid & 1;
    const int wm    = wid & 3;
    const int wn    = wid >> 2;

    const float* brow_f = GATHER ? emb + (size_t)X[t * 128 + row] * EE : nullptr;

    float acc[2][8][4];
#pragma unroll
    for (int mt = 0; mt < 2; mt++)
#pragma unroll
        for (int j = 0; j < 8; j++)
#pragma unroll
            for (int e = 0; e < 4; e++) acc[mt][j][e] = 0.0f;

    u32 aoff[2], boff[4];
#pragma unroll
    for (int mt = 0; mt < 2; mt++)
        aoff[mt] = (u32)((wm * 32 + mt * 16 + (lane & 15)) * PITCH + (lane >> 4) * 16);
#pragma unroll
    for (int nt = 0; nt < 4; nt++)
        boff[nt] = (u32)((wn * 64 + nt * 16 + (lane & 7) + ((lane >> 3) & 1) * 8) * PITCH
                         + (lane >> 4) * 16);

    auto issue = [&](int c) {
        const u32 tb = smb + (u32)((c & 1) * BUFB);
        const int k0 = c * 64;
        const __nv_bfloat16* ah = g_wh + (size_t)(nbase + row) * Kpad + k0 + sub * 32;
        const __nv_bfloat16* al = g_wl + (size_t)(nbase + row) * Kpad + k0 + sub * 32;
#pragma unroll
        for (int i = 0; i < 4; i++) {
            u32 so = (u32)(row * PITCH + sub * 64 + i * 16);
            cpa16(tb + so, ah + i * 8);
            cpa16(tb + TILE_B + so, al + i * 8);
        }
        if (!GATHER) {
            const __nv_bfloat16* bh = g_y0h + ((size_t)t * 128 + row) * 1024 + k0 + sub * 32;
            const __nv_bfloat16* bl = g_y0l + ((size_t)t * 128 + row) * 1024 + k0 + sub * 32;
#pragma unroll
            for (int i = 0; i < 4; i++) {
                u32 so = (u32)(row * PITCH + sub * 64 + i * 16);
                cpa16(tb + 2 * TILE_B + so, bh + i * 8);
                cpa16(tb + 3 * TILE_B + so, bl + i * 8);
            }
        } else {
            char* buf = sm + (c & 1) * BUFB;
#pragma unroll
            for (int i = 0; i < 8; i++) {
                int k = k0 + sub * 32 + i * 4;
                float4 v = (k + 4 <= EE) ? *(const float4*)(brow_f + k) : make_float4(0, 0, 0, 0);
                u64 ph = 0, pl = 0;
#pragma unroll
                for (int jx = 0; jx < 4; jx++) {
                    float f = (&v.x)[jx];
                    __nv_bfloat16 hb = __float2bfloat16(f);
                    __nv_bfloat16 lb = __float2bfloat16(f - __bfloat162float(hb));
                    ph |= (u64)__bfloat16_as_ushort(hb) << (16 * jx);
                    pl |= (u64)__bfloat16_as_ushort(lb) << (16 * jx);
                }
                u32 so = (u32)(row * PITCH + sub * 64 + i * 8);
                *(u64*)(buf + 2 * TILE_B + so) = ph;
                *(u64*)(buf + 3 * TILE_B + so) = pl;
            }
        }
        asm volatile("cp.async.commit_group;" ::: "memory");
    };

    issue(0);
    for (int c = 0; c < nch; c++) {
        if (c + 1 < nch) {
            issue(c + 1);
            asm volatile("cp.async.wait_group 1;" ::: "memory");
        } else {
            asm volatile("cp.async.wait_group 0;" ::: "memory");
        }
        __syncthreads();

        const u32 tb = smb + (u32)((c & 1) * BUFB);
#pragma unroll
        for (int ks = 0; ks < 4; ks++) {
            const u32 kb = (u32)(ks * 32);
            u32 ah[2][4], al[2][4], bh[4][4], bl[4][4];
#pragma unroll
            for (int mt = 0; mt < 2; mt++) {
                ldsm4(ah[mt][0], ah[mt][1], ah[mt][2], ah[mt][3], tb + aoff[mt] + kb);
                ldsm4(al[mt][0], al[mt][1], al[mt][2], al[mt][3], tb + TILE_B + aoff[mt] + kb);
            }
#pragma unroll
            for (int nt = 0; nt < 4; nt++) {
                ldsm4(bh[nt][0], bh[nt][1], bh[nt][2], bh[nt][3], tb + 2 * TILE_B + boff[nt] + kb);
                ldsm4(bl[nt][0], bl[nt][1], bl[nt][2], bl[nt][3], tb + 3 * TILE_B + boff[nt] + kb);
            }
#pragma unroll
            for (int mt = 0; mt < 2; mt++)
#pragma unroll
                for (int nt = 0; nt < 4; nt++)
#pragma unroll
                    for (int hf = 0; hf < 2; hf++) {
                        float* cc = acc[mt][nt * 2 + hf];
                        mma16816(cc, ah[mt], bh[nt][hf], bh[nt][hf + 2]);
                        mma16816(cc, ah[mt], bl[nt][hf], bl[nt][hf + 2]);
                        mma16816(cc, al[mt], bh[nt][hf], bh[nt][hf + 2]);
                    }
        }
        __syncthreads();
    }

#pragma unroll
    for (int mt = 0; mt < 2; mt++) {
        const int m0 = wm * 32 + mt * 16 + (lane >> 2);
        const int m1 = m0 + 8;
        const float bv0 = bias[nbase + m0];
        const float bv1 = bias[nbase + m1];
        float* d0 = g_gi + ((size_t)t * NCOL + nbase + m0) * 128;
        float* d1 = g_gi + ((size_t)t * NCOL + nbase + m1) * 128;
#pragma unroll
        for (int j = 0; j < 8; j++) {
            const int b = wn * 64 + j * 8 + (lane & 3) * 2;
            *(float2*)(d0 + b) = make_float2(acc[mt][j][0] + bv0, acc[mt][j][1] + bv0);
            *(float2*)(d1 + b) = make_float2(acc[mt][j][2] + bv1, acc[mt][j][3] + bv1);
        }
    }
}

// ================= HMMA persistent recurrence =================
// 128 CTAs: dir = cta>>6, jbase = (cta&63)*8.
// A = Whh slice, 32 rows (r j0-7, z j0-7, n j0-7, 8 pad) x 512 k, bf16 hi/lo, smem-resident.
// B = h [128 b][512 k] bf16 hi/lo, streamed in 128-k chunks, double-buffered.
// Warp w covers b [16w, 16w+16); lane owns j = lane>>2, 4 b values.
#define A_PITCH 1040
#define A_PLANE (32 * A_PITCH)                 // 33280
#define A_BYTES (2 * A_PLANE)                  // 66560
#define B_PITCH 272
#define B_PLANE (128 * B_PITCH)                // 34816
#define B_CHUNK (2 * B_PLANE)                  // 69632
#define RECUR_SMEM (A_BYTES + 2 * B_CHUNK)     // 205824

template <bool WRITE_Y>
__global__ __launch_bounds__(256, 1) void recur_kernel(
    const float* __restrict__ Whh, const float* __restrict__ bhh)
{
    extern __shared__ __align__(16) char sm[];
    const u32 smA = (u32)__cvta_generic_to_shared(sm);
    const u32 smB = smA + A_BYTES;

    const int cta   = blockIdx.x;
    const int d     = cta >> 6;
    const int jbase = (cta & 63) * 8;
    const int tid   = threadIdx.x;
    const int w     = tid >> 5;
    const int lane  = tid & 31;

    // load static A (Whh slice) -> bf16 hi/lo, rows [g*8+j], pad rows zero
    for (int idx = tid; idx < 32 * 512; idx += 256) {
        int rrow = idx >> 9, k = idx & 511;
        float v = 0.0f;
        if (rrow < 24) {
            int g = rrow >> 3, jj = rrow & 7;
            v = Whh[((size_t)d * G3 + g * HH + jbase + jj) * HH + k];
        }
        __nv_bfloat16 hb = __float2bfloat16(v);
        __nv_bfloat16 lb = __float2bfloat16(v - __bfloat162float(hb));
        char* base = sm + rrow * A_PITCH + k * 2;
        *(__nv_bfloat16*)base = hb;
        *(__nv_bfloat16*)(base + A_PLANE) = lb;
    }
    const int jq = lane >> 2;
    const int jg = jbase + jq;
    const float bh_r = bhh[(size_t)d * G3 + jg];
    const float bh_z = bhh[(size_t)d * G3 + HH + jg];
    const float bh_n = bhh[(size_t)d * G3 + 2 * HH + jg];
    __syncthreads();

    // ldmatrix offsets
    u32 aoff[2][2];
#pragma unroll
    for (int pl = 0; pl < 2; pl++)
#pragma unroll
        for (int mt = 0; mt < 2; mt++)
            aoff[pl][mt] = smA + (u32)(pl * A_PLANE + (mt * 16 + (lane & 15)) * A_PITCH + (lane >> 4) * 16);
    const u32 brow_off = (u32)((16 * w + (lane & 7) + ((lane >> 3) & 1) * 8) * B_PITCH + (lane >> 4) * 16);

    // staging mapping: thread -> (b row, half)
    const int srow  = tid & 127;
    const int shalf = tid >> 7;

    float hold[2][2];
    hold[0][0] = hold[0][1] = hold[1][0] = hold[1][1] = 0.0f;

    for (int t = 0; t < SQ; t++) {
        const int pr = t & 1, pw = pr ^ 1;
        const __nv_bfloat16* hsh = &g_hbh[pr][d][0][0];
        const __nv_bfloat16* hsl = &g_hbl[pr][d][0][0];

        auto stage = [&](int c) {
            const u32 db = smB + (u32)((c & 1) * B_CHUNK);
#pragma unroll
            for (int i = 0; i < 8; i++) {
                u32 so = (u32)(srow * B_PITCH + shalf * 128 + i * 16);
                const int eo = srow * 512 + c * 128 + shalf * 64 + i * 8;
                cpa16(db + so, hsh + eo);
                cpa16(db + B_PLANE + so, hsl + eo);
            }
            asm volatile("cp.async.commit_group;" ::: "memory");
        };

        stage(0);

        // hoisted gi loads: 3 gates x 2 ntiles x float2
        const float* gbase = g_gi + (size_t)t * NCOL * 128 + (size_t)(d * G3 + jg) * 128;
        float2 gi_r[2], gi_z[2], gi_n[2];
#pragma unroll
        for (int nt = 0; nt < 2; nt++) {
            const int b = 16 * w + nt * 8 + (lane & 3) * 2;
            gi_r[nt] = *(const float2*)(gbase + b);
            gi_z[nt] = *(const float2*)(gbase + (size_t)HH * 128 + b);
            gi_n[nt] = *(const float2*)(gbase + (size_t)2 * HH * 128 + b);
        }

        float acc[2][2][4];
#pragma unroll
        for (int mt = 0; mt < 2; mt++)
#pragma unroll
            for (int nt = 0; nt < 2; nt++)
#pragma unroll
                for (int e = 0; e < 4; e++) acc[mt][nt][e] = 0.0f;

        for (int c = 0; c < 4; c++) {
            if (c + 1 < 4) {
                stage(c + 1);
                asm volatile("cp.async.wait_group 1;" ::: "memory");
            } else {
                asm volatile("cp.async.wait_group 0;" ::: "memory");
            }
            __syncthreads();

            const u32 bb = smB + (u32)((c & 1) * B_CHUNK) + brow_off;
            const u32 akb = (u32)(c * 256);    // 128 k * 2B
#pragma unroll
            for (int ks = 0; ks < 8; ks++) {
                const u32 kb = (u32)(ks * 32);
                u32 ah[2][4], al[2][4], bhf[4], blf[4];
#pragma unroll
                for (int mt = 0; mt < 2; mt++) {
                    ldsm4(ah[mt][0], ah[mt][1], ah[mt][2], ah[mt][3], aoff[0][mt] + akb + kb);
                    ldsm4(al[mt][0], al[mt][1], al[mt][2], al[mt][3], aoff[1][mt] + akb + kb);
                }
                ldsm4(bhf[0], bhf[1], bhf[2], bhf[3], bb + kb);
                ldsm4(blf[0], blf[1], blf[2], blf[3], bb + B_PLANE + kb);
#pragma unroll
                for (int mt = 0; mt < 2; mt++)
#pragma unroll
                    for (int nt = 0; nt < 2; nt++) {
                        float* cc = acc[mt][nt];
                        mma16816(cc, ah[mt], bhf[nt], bhf[nt + 2]);
                        mma16816(cc, ah[mt], blf[nt], blf[nt + 2]);
                        mma16816(cc, al[mt], bhf[nt], bhf[nt + 2]);
                    }
            }
            __syncthreads();
        }

        // epilogue: lane owns j=jq, b = 16w + nt*8 + 2(lane&3) + e
#pragma unroll
        for (int nt = 0; nt < 2; nt++) {
            const int b = 16 * w + nt * 8 + (lane & 3) * 2;
#pragma unroll
            for (int e = 0; e < 2; e++) {
                float ghr = acc[0][nt][e]     + bh_r + ((e == 0) ? gi_r[nt].x : gi_r[nt].y);
                float ghz = acc[0][nt][2 + e] + bh_z + ((e == 0) ? gi_z[nt].x : gi_z[nt].y);
                float ghn = acc[1][nt][e]     + bh_n + ((e == 0) ? gi_n[nt].x : gi_n[nt].y);
                float r = 1.0f / (1.0f + expf(-ghr));
                float z = 1.0f / (1.0f + expf(-ghz));
                float n = tanhf(ghn + r * (acc[1][nt][e] + bh_n) - (acc[1][nt][e] + bh_n) + r * 0.0f);
                // NOTE: careful formula below (r multiplies only gh part)
                (void)n;
                float gh_only = acc[1][nt][e] + bh_n;
                float gi_only = (e == 0) ? gi_n[nt].x : gi_n[nt].y;
                n = tanhf(gi_only + r * gh_only);
                float hnew = (1.0f - z) * n + z * hold[nt][e];
                hold[nt][e] = hnew;
                __nv_bfloat16 hb = __float2bfloat16(hnew);
                __nv_bfloat16 lb = __float2bfloat16(hnew - __bfloat162float(hb));
                g_hbh[pw][d][b + e][jg] = hb;
                g_hbl[pw][d][b + e][jg] = lb;
                if (WRITE_Y) {
                    size_t yo = ((size_t)t * 128 + b + e) * 1024 + d * HH + jg;
                    g_y0h[yo] = hb;
                    g_y0l[yo] = lb;
                }
            }
        }

        if (t < SQ - 1) {
            __threadfence();
            __syncthreads();
            if (tid == 0) {
                atomicAdd(&g_bar, 1u);
                const unsigned target = (unsigned)(t + 1) * gridDim.x;
                while (*(volatile unsigned*)&g_bar < target) { }
            }
            __syncthreads();
            __threadfence();
        }
    }
}

__global__ void final_kernel(const float* __restrict__ Ws, const float* __restrict__ bs,
                             float* __restrict__ out)
{
    const int b = threadIdx.x;
    float l0 = bs[0], l1 = bs[1];
#pragma unroll 2
    for (int d = 0; d < 2; d++) {
        for (int jj = 0; jj < HH; jj++) {
            float h = __bfloat162float(g_hbh[0][d][b][jj]) + __bfloat162float(g_hbl[0][d][b][jj]);
            int c = d * HH + jj;
            l0 = fmaf(h, Ws[c], l0);
            l1 = fmaf(h, Ws[1024 + c], l1);
        }
    }
    float m = fmaxf(l0, l1);
    float lse = m + logf(expf(l0 - m) + expf(l1 - m));
    out[b * 2 + 0] = l0 - lse;
    out[b * 2 + 1] = l1 - lse;
}

extern "C" void kernel_launch(void* const* d_in, const int* in_sizes, int n_in,
                              void* d_out, int out_size)
{
    const int*   X    = (const int*)  d_in[0];
    const float* emb  = (const float*)d_in[1];
    const float* Wih0 = (const float*)d_in[2];
    const float* Whh0 = (const float*)d_in[3];
    const float* bih0 = (const float*)d_in[4];
    const float* bhh0 = (const float*)d_in[5];
    const float* Wih1 = (const float*)d_in[6];
    const float* Whh1 = (const float*)d_in[7];
    const float* bih1 = (const float*)d_in[8];
    const float* bhh1 = (const float*)d_in[9];
    const float* Ws   = (const float*)d_in[10];
    const float* bs   = (const float*)d_in[11];
    float* out = (float*)d_out;

    cudaFuncSetAttribute(recur_kernel<true>,  cudaFuncAttributeMaxDynamicSharedMemorySize, RECUR_SMEM);
    cudaFuncSetAttribute(recur_kernel<false>, cudaFuncAttributeMaxDynamicSharedMemorySize, RECUR_SMEM);
    cudaFuncSetAttribute(gemm_tc<true>,  cudaFuncAttributeMaxDynamicSharedMemorySize, GEMM_SMEM);
    cudaFuncSetAttribute(gemm_tc<false>, cudaFuncAttributeMaxDynamicSharedMemorySize, GEMM_SMEM);

    dim3 ggrid(NCOL / 128, SQ);

    // layer 0
    init_kernel<<<128, 256>>>();
    wsplit_kernel<<<480, 256>>>(Wih0, EE, 320);
    gemm_tc<true><<<ggrid, 256, GEMM_SMEM>>>(emb, X, bih0, 320, 5);
    recur_kernel<true><<<128, 256, RECUR_SMEM>>>(Whh0, bhh0);

    // layer 1
    init_kernel<<<128, 256>>>();
    wsplit_kernel<<<480, 256>>>(Wih1, 1024, 1024);
    gemm_tc<false><<<ggrid, 256, GEMM_SMEM>>>(nullptr, nullptr, bih1, 1024, 16);
    recur_kernel<false><<<128, 256, RECUR_SMEM>>>(Whh1, bhh1);

    final_kernel<<<1, 128>>>(Ws, bs, out);
}